// round 9
// baseline (speedup 1.0000x reference)
#include <cuda_runtime.h>
#include <cuda_bf16.h>

#define VOCAB    128000
#define HISTLEN  2048
#define TOPK     15
#define NTHR     1024

// monotone map float -> unsigned (total order; NaN orders above +inf) + inverse
__device__ __forceinline__ unsigned ordered(float f) {
    unsigned u = __float_as_uint(f);
    return u ^ ((u & 0x80000000u) ? 0xFFFFFFFFu : 0x80000000u);
}
__device__ __forceinline__ float unordered(unsigned x) {
    unsigned u = (x & 0x80000000u) ? (x ^ 0x80000000u) : (x ^ 0xFFFFFFFFu);
    return __uint_as_float(u);
}

// Single block does EVERYTHING: no device globals, no cross-block traffic.
__global__ void __launch_bounds__(NTHR, 1)
k_sample(const float* __restrict__ logits,
         const int*   __restrict__ y,
         const float* __restrict__ noise,
         float* __restrict__ out, int out_size) {   // <-- FLOAT output this round
    __shared__ unsigned           bm[VOCAB / 32];   // 16 KB membership bitmap
    __shared__ unsigned long long red[NTHR];        // 8 KB reduction scratch
    __shared__ unsigned long long sh_top[TOPK];
    __shared__ float              sh_piv, sh_lmax, sh_S;

    const int tid = threadIdx.x;
    const bool full = (out_size >= HISTLEN + 2);    // [samples, y(2048), sample]

    // ---- 1. membership bitmap + history copy (AS FLOAT VALUES) ------------
    for (int j = tid; j < VOCAB / 32; j += NTHR) bm[j] = 0u;
    __syncthreads();
    for (int t = tid; t < HISTLEN; t += NTHR) {
        int p = y[t];
        if (full) out[1 + t] = (float)p;            // exact: p < 2^24
        p = min(max(p, 0), VOCAB - 1);              // clamp: OOB impossible
        atomicOr(&bm[p >> 5], 1u << (p & 31));
    }
    __syncthreads();

    // penalized logit: depends only on the ORIGINAL logit (history duplicates
    // harmless); _rn ops are bit-identical to the f32 reference
    auto plog = [&](int i) -> float {
        float raw = logits[i];
        if ((bm[i >> 5] >> (i & 31)) & 1u)
            raw = (raw < 0.0f) ? __fmul_rn(raw, 1.35f) : __fdiv_rn(raw, 1.35f);
        return raw;
    };

    // ---- 2. per-thread top-15 (unique value||~index keys, descending) -----
    unsigned long long loc[TOPK];
    #pragma unroll
    for (int k = 0; k < TOPK; k++) loc[k] = 0ull;   // 0 < any real key
    for (int i = tid; i < VOCAB; i += NTHR) {
        unsigned long long key = ((unsigned long long)ordered(plog(i)) << 32)
                               | (unsigned long long)(0xFFFFFFFFu - (unsigned)i);
        if (key > loc[TOPK - 1]) {
            int j = TOPK - 1;
            while (j > 0 && loc[j - 1] < key) { loc[j] = loc[j - 1]; j--; }
            loc[j] = key;
        }
    }

    // ---- 3. exact global top-15: 15 block-max extractions ------------------
    int pos = 0;
    for (int k = 0; k < TOPK; k++) {
        red[tid] = (pos < TOPK) ? loc[pos] : 0ull;
        __syncthreads();
        for (int s = NTHR / 2; s > 0; s >>= 1) {
            if (tid < s) { unsigned long long o = red[tid + s]; if (o > red[tid]) red[tid] = o; }
            __syncthreads();
        }
        unsigned long long win = red[0];
        __syncthreads();
        if (pos < TOPK && loc[pos] == win) pos++;   // unique keys: exactly one pops
        if (tid == 0) sh_top[k] = win;
    }
    __syncthreads();

    if (tid == 0) {
        float lmax = unordered((unsigned)(sh_top[0] >> 32));
        float piv  = unordered((unsigned)(sh_top[TOPK - 1] >> 32));
        float S = 0.0f;                             // softmax denom over the kept set
        for (int k = 0; k < TOPK; k++)
            S += expf(unordered((unsigned)(sh_top[k] >> 32)) - lmax);
        sh_lmax = lmax; sh_piv = piv; sh_S = S;
    }
    __syncthreads();

    // ---- 4. argmax(probs/noise) via ordered 64-bit keys ---------------------
    // kept: (exp(l-lmax)/S)/noise ; masked: 0/noise (exact +-0 / NaN like ref).
    // +-0 unify to ONE key (first-index tie-break, IEEE +0==-0 under jnp.argmax);
    // NaN keys order above everything (jnp.argmax NaN propagation).
    const float piv = sh_piv, lmax = sh_lmax, S = sh_S;
    unsigned long long best = 0ull;
    for (int i = tid; i < VOCAB; i += NTHR) {
        float l = plog(i);
        float nz = noise[i];
        float v = (l >= piv) ? __fdiv_rn(__fdiv_rn(expf(l - lmax), S), nz)
                             : __fdiv_rn(0.0f, nz);
        unsigned ov = (v == 0.0f) ? 0x80000000u : ordered(v);
        unsigned long long key = ((unsigned long long)ov << 32)
                               | (unsigned long long)(0xFFFFFFFFu - (unsigned)i);
        if (key > best) best = key;
    }
    red[tid] = best;
    __syncthreads();
    for (int s = NTHR / 2; s > 0; s >>= 1) {
        if (tid < s) { unsigned long long o = red[tid + s]; if (o > red[tid]) red[tid] = o; }
        __syncthreads();
    }

    // ---- 5. sample writes (AS FLOAT VALUES) ---------------------------------
    int idx = (int)(0xFFFFFFFFu - (unsigned)(red[0] & 0xFFFFFFFFull));
    float fidx = (float)idx;                        // exact conversion
    if (full) {
        if (tid == 0) { out[0] = fidx; out[1 + HISTLEN] = fidx; }
        for (int j = HISTLEN + 2 + tid; j < out_size; j += NTHR) out[j] = fidx;
    } else {
        for (int j = tid; j < out_size; j += NTHR) out[j] = fidx;
    }
}

extern "C" void kernel_launch(void* const* d_in, const int* in_sizes, int n_in,
                              void* d_out, int out_size) {
    // y = the size-2048 tensor; among the remaining two (metadata order),
    // logits precedes noise (mapping A, per documented contract).
    int iy = 1;
    for (int i = 0; i < n_in; i++) if (in_sizes[i] == HISTLEN) { iy = i; break; }
    int fl[2]; int nf = 0;
    for (int i = 0; i < n_in && nf < 2; i++) if (i != iy) fl[nf++] = i;

    const float* logits = (const float*)d_in[fl[0]];
    const float* noise  = (const float*)d_in[fl[1]];
    const int*   y      = (const int*)d_in[iy];

    k_sample<<<1, NTHR>>>(logits, y, noise, (float*)d_out, out_size);
}

// round 10
// speedup vs baseline: 11.0458x; 11.0458x over previous
#include <cuda_runtime.h>
#include <cuda_bf16.h>

#define VOCAB    128000
#define HISTLEN  2048
#define TOPK     15
#define NBLK     125          // 125 * 1024 == 128000 exactly
#define NTHR     1024
#define NWARP    32

// ---------------- device scratch (allocations forbidden) ----------------
__device__ unsigned           g_bitmap[VOCAB / 32];       // penalized membership
__device__ unsigned long long g_btop[NBLK * TOPK];        // per-block top keys
__device__ float              g_lmax, g_pivot, g_S;
__device__ unsigned long long g_amax;

// monotone map float -> unsigned (total order; NaN above +inf) + inverse
__device__ __forceinline__ unsigned ordered(float f) {
    unsigned u = __float_as_uint(f);
    return u ^ ((u & 0x80000000u) ? 0xFFFFFFFFu : 0x80000000u);
}
__device__ __forceinline__ float unordered(unsigned x) {
    unsigned u = (x & 0x80000000u) ? (x ^ 0x80000000u) : (x ^ 0xFFFFFFFFu);
    return __uint_as_float(u);
}

// penalized logit: depends only on the ORIGINAL logit (history duplicates
// harmless); _rn ops are bit-identical to the f32 reference
__device__ __forceinline__ float plog_at(const float* __restrict__ logits, int i) {
    float raw = logits[i];
    if ((g_bitmap[i >> 5] >> (i & 31)) & 1u)
        raw = (raw < 0.0f) ? __fmul_rn(raw, 1.35f) : __fdiv_rn(raw, 1.35f);
    return raw;
}

// unique key = ordered(value) || ~index  (strictly totally ordered)
__device__ __forceinline__ unsigned long long make_key(float v, int i) {
    return ((unsigned long long)ordered(v) << 32)
         | (unsigned long long)(0xFFFFFFFFu - (unsigned)i);
}

// warp-collective max of a ull key
__device__ __forceinline__ unsigned long long warp_max(unsigned long long k) {
    #pragma unroll
    for (int off = 16; off; off >>= 1) {
        unsigned long long o = __shfl_xor_sync(0xffffffffu, k, off);
        if (o > k) k = o;
    }
    return k;
}

// KA (1 block): reset state, build membership bitmap, copy y (AS FLOATS)
__global__ void kA_prep(const int* __restrict__ y, float* __restrict__ out,
                        int out_size) {
    int tid = threadIdx.x;
    for (int j = tid; j < VOCAB / 32; j += NTHR) g_bitmap[j] = 0u;
    if (tid == 0) g_amax = 0ull;
    __syncthreads();
    const bool full = (out_size >= HISTLEN + 2);
    for (int t = tid; t < HISTLEN; t += NTHR) {
        int p = y[t];
        if (full) out[1 + t] = (float)p;          // exact: p < 2^24
        p = min(max(p, 0), VOCAB - 1);            // clamp: OOB impossible
        atomicOr(&g_bitmap[p >> 5], 1u << (p & 31));
    }
}

// KB (125 blocks): exact per-block top-15 keys -> g_btop (block-local only)
__global__ void __launch_bounds__(NTHR, 1)
kB_blocktop(const float* __restrict__ logits) {
    __shared__ unsigned long long swtop[NWARP * TOPK];   // 480 warp candidates
    int tid = threadIdx.x, lane = tid & 31, w = tid >> 5;
    unsigned long long cur = make_key(plog_at(logits, blockIdx.x * NTHR + tid),
                                      blockIdx.x * NTHR + tid);
    #pragma unroll
    for (int k = 0; k < TOPK; k++) {              // warp top-15: unique keys ->
        unsigned long long m = warp_max(cur);     // exactly one owner pops
        if (lane == 0) swtop[w * TOPK + k] = m;
        if (cur == m) cur = 0ull;
    }
    __syncthreads();
    if (w == 0) {                                 // merge 480 -> block top-15
        for (int k = 0; k < TOPK; k++) {
            unsigned long long lm = 0ull; int lp = 0;
            for (int j = lane; j < NWARP * TOPK; j += 32) {
                unsigned long long x = swtop[j];
                if (x > lm) { lm = x; lp = j; }
            }
            unsigned long long m = warp_max(lm);
            if (lm == m && lm != 0ull) swtop[lp] = 0ull;  // unique: one owner
            __syncwarp();
            if (lane == 0) g_btop[blockIdx.x * TOPK + k] = m;
        }
    }
}

// KC (1 block): merge 1875 block-top keys -> lmax, pivot, softmax denom S
__global__ void kC_pivot() {
    __shared__ unsigned long long sall[NBLK * TOPK];     // 1875
    __shared__ float top[TOPK];
    int tid = threadIdx.x, lane = tid & 31, w = tid >> 5;
    for (int j = tid; j < NBLK * TOPK; j += NTHR) sall[j] = g_btop[j];
    __syncthreads();
    if (w == 0) {
        for (int k = 0; k < TOPK; k++) {
            unsigned long long lm = 0ull; int lp = 0;
            for (int j = lane; j < NBLK * TOPK; j += 32) {
                unsigned long long x = sall[j];
                if (x > lm) { lm = x; lp = j; }
            }
            unsigned long long m = warp_max(lm);
            if (lm == m && lm != 0ull) sall[lp] = 0ull;
            __syncwarp();
            if (lane == 0) top[k] = unordered((unsigned)(m >> 32));
        }
        if (lane == 0) {
            float lmax = top[0];
            float S = 0.0f;                       // kept set IS these 15 values
            for (int k = 0; k < TOPK; k++) S += expf(top[k] - lmax);
            g_lmax = lmax; g_pivot = top[TOPK - 1]; g_S = S;
        }
    }
}

// KD (125 blocks): argmax(probs/noise). kept: (exp(l-lmax)/S)/noise; masked:
// 0/noise (exact +-0 / NaN like ref). +-0 unify to one key (first-index ties,
// IEEE +0==-0 under jnp.argmax); NaN keys order above all (NaN propagation).
__global__ void __launch_bounds__(NTHR, 1)
kD_argmax(const float* __restrict__ logits, const float* __restrict__ noise) {
    __shared__ unsigned long long red[NTHR];
    int tid = threadIdx.x;
    int i = blockIdx.x * NTHR + tid;
    float piv = g_pivot, lmax = g_lmax, S = g_S;
    float l = plog_at(logits, i);
    float nz = noise[i];
    float v = (l >= piv) ? __fdiv_rn(__fdiv_rn(expf(l - lmax), S), nz)
                         : __fdiv_rn(0.0f, nz);
    unsigned ov = (v == 0.0f) ? 0x80000000u : ordered(v);
    red[tid] = ((unsigned long long)ov << 32)
             | (unsigned long long)(0xFFFFFFFFu - (unsigned)i);
    __syncthreads();
    for (int s = NTHR / 2; s > 0; s >>= 1) {
        if (tid < s) { unsigned long long o = red[tid + s]; if (o > red[tid]) red[tid] = o; }
        __syncthreads();
    }
    if (tid == 0) atomicMax(&g_amax, red[0]);
}

// KE (1 thread): emit sample (AS FLOAT) at both positions
__global__ void kE_write(float* __restrict__ out, int out_size) {
    int idx = (int)(0xFFFFFFFFu - (unsigned)(g_amax & 0xFFFFFFFFull));
    float fidx = (float)idx;
    out[0] = fidx;                                 // samples
    if (out_size >= HISTLEN + 2) out[1 + HISTLEN] = fidx;  // y_new tail
    for (int j = HISTLEN + 2; j < out_size; j++) out[j] = fidx;
}

extern "C" void kernel_launch(void* const* d_in, const int* in_sizes, int n_in,
                              void* d_out, int out_size) {
    // y = the size-2048 tensor; among the remaining two (metadata order),
    // logits precedes noise (mapping A — validated in round 9).
    int iy = 1;
    for (int i = 0; i < n_in; i++) if (in_sizes[i] == HISTLEN) { iy = i; break; }
    int fl[2]; int nf = 0;
    for (int i = 0; i < n_in && nf < 2; i++) if (i != iy) fl[nf++] = i;

    const float* logits = (const float*)d_in[fl[0]];
    const float* noise  = (const float*)d_in[fl[1]];
    const int*   y      = (const int*)d_in[iy];
    float* out = (float*)d_out;

    kA_prep    <<<1,    NTHR>>>(y, out, out_size);
    kB_blocktop<<<NBLK, NTHR>>>(logits);
    kC_pivot   <<<1,    NTHR>>>();
    kD_argmax  <<<NBLK, NTHR>>>(logits, noise);
    kE_write   <<<1,    1>>>(out, out_size);
}